// round 15
// baseline (speedup 1.0000x reference)
#include <cuda_runtime.h>
#include <cuda_bf16.h>
#include <cuda_fp16.h>
#include <cstdint>

// ---------------------------------------------------------------------------
// Classifier: out[e] = MLP(concat(x_drug[i_e], x_disease[j_e]))
// SINGLE fused persistent kernel (444 blocks = exact 3/SM residency):
//   Phase A (blocks 0-13): W1 hi/lo fp16 fragment build (split-precision).
//   Phase B: layer-1 per-node GEMM on tensor cores (x=xh+xl, W1=Wh+Wl;
//            xh@Wh + xl@Wh + xh@Wl in fp32 -> err ~1e-7), fp16 h tables.
//   Phase C: per-edge MLP: h = lrelu(hd[i]+he[j]) in half2 -> fp16 smem;
//            layers 2/3 on mma.m16n8k16.f16 (fp32 accum) with composing
//            fragment layouts; layer-4 dot + shfl reduce. Warp-autonomous.
// Inter-phase sync: device counters + volatile flags (read-polling; atomics
// only on the producer side). g_sync reset per replay via captured memset.
// ---------------------------------------------------------------------------

typedef unsigned long long ull;

#define MAX_NODES 16384
__device__ __half g_hd[MAX_NODES * 128];
__device__ __half g_he[MAX_NODES * 128];
__device__ int    g_idx64;     // 1 if edge index buffer is int64, 0 if int32

#define NFRAG (7 * 16 * 32)               // 3584 uint2 per set
__device__ uint2 g_whf[2][NFRAG];         // [0]=drug slice, [1]=disease slice
__device__ uint2 g_wlf[2][NFRAG];

// [0]=frag cnt, [1]=node cnt, [2]=frag flag, [3]=node flag (memset each launch)
__device__ unsigned g_sync[4];

__device__ __forceinline__ float lrelu(float v) {
    return v >= 0.0f ? v : 0.01f * v;
}
__device__ __forceinline__ uint32_t h2(float a, float b) {
    __half2 h = __floats2half2_rn(a, b);   // x(lo)=a, y(hi)=b
    return *(uint32_t*)&h;
}
__device__ __forceinline__ uint32_t haddlrelu2(uint32_t a, uint32_t b,
                                               __half2 c01) {
    __half2 s = __hadd2(*(__half2*)&a, *(__half2*)&b);
    __half2 r = __hmax2(s, __hmul2(s, c01));
    return *(uint32_t*)&r;
}
__device__ __forceinline__ long long load_idx(const void* ell, long long pos,
                                              int is64) {
    if (is64) return ((const long long*)ell)[pos];
    return (long long)((const int*)ell)[pos];
}
__device__ __forceinline__ void hmma16(float d[4], uint32_t a0, uint32_t a1,
                                       uint32_t a2, uint32_t a3,
                                       uint32_t b0, uint32_t b1) {
    asm volatile(
        "mma.sync.aligned.m16n8k16.row.col.f32.f16.f16.f32 "
        "{%0,%1,%2,%3}, {%4,%5,%6,%7}, {%8,%9}, {%0,%1,%2,%3};"
        : "+f"(d[0]), "+f"(d[1]), "+f"(d[2]), "+f"(d[3])
        : "r"(a0), "r"(a1), "r"(a2), "r"(a3), "r"(b0), "r"(b1));
}

#define NNB   64
#define XS_RS 240                         // 112 halves = 224B + 16 pad
#define EPB   128
#define NTHR  256
#define HS_RS 272                         // 256B + 16 pad
#define GRID  (3 * 148)

__global__ void __launch_bounds__(NTHR, 3)
fused_kernel(const float* __restrict__ xd,  const float* __restrict__ xs,
             const void*  __restrict__ ell,
             const float* __restrict__ W1,  const float* __restrict__ b1,
             const float* __restrict__ W2,  const float* __restrict__ b2,
             const float* __restrict__ W3,  const float* __restrict__ b3,
             const float* __restrict__ W4,  const float* __restrict__ b4,
             float* __restrict__ out,
             int n_drug, int n_dis, int nb_drug, int nb_dis,
             int E, int n_tiles) {
    __shared__ char  hsraw[8 * 16 * HS_RS];   // 34816 B (union: node xh/xl)
    __shared__ uint4 wfr[8 * 2 * 32];         // W2 frags (8 KB, edge phase)

    const int tid  = threadIdx.x;
    const int bid  = blockIdx.x;
    const int warp = tid >> 5;
    const int lane = tid & 31;
    volatile unsigned* sync = g_sync;

    // ---- stage W2 fp16 B-fragments (independent of node tables) ----
    for (int idx = tid; idx < 512; idx += NTHR) {
        int ln  = idx & 31;
        int nbp = (idx >> 5) & 1;
        int ks  = idx >> 6;
        int n0  = 16 * nbp + (ln >> 2);
        int n1  = n0 + 8;
        int kb  = 16 * ks + 2 * (ln & 3);
        uint4 b;
        b.x = h2(W2[kb * 32 + n0],       W2[(kb + 1) * 32 + n0]);
        b.y = h2(W2[(kb + 8) * 32 + n0], W2[(kb + 9) * 32 + n0]);
        b.z = h2(W2[kb * 32 + n1],       W2[(kb + 1) * 32 + n1]);
        b.w = h2(W2[(kb + 8) * 32 + n1], W2[(kb + 9) * 32 + n1]);
        wfr[idx] = b;
    }

    // ======================= Phase A: W1 frag build =======================
    if (bid < 14) {
        float* wsl = (float*)hsraw;           // 16*128 floats = 8 KB
        const int sel = bid / 7;
        const int ks  = bid % 7;

        if (bid == 0 && tid == 0) {
            int ok64 = 1;
#pragma unroll
            for (int t = 0; t < 8; t++) {
                long long v = ((const long long*)ell)[t];
                if (v < 0 || v >= 1000000) ok64 = 0;
            }
            g_idx64 = ok64;
        }

        const float* w = W1 + sel * 100 * 128 + 16 * ks * 128;
        const int krows = (100 - 16 * ks) < 16 ? (100 - 16 * ks) : 16;

        for (int i = tid; i < 16 * 32; i += NTHR) {
            float4 v = make_float4(0.f, 0.f, 0.f, 0.f);
            if ((i >> 5) < krows) v = ((const float4*)w)[i];
            ((float4*)wsl)[i] = v;
        }
        __syncthreads();

        for (int i = tid; i < 512; i += NTHR) {
            int ln = i & 31;
            int nb = i >> 5;
            int nn = 8 * nb + (ln >> 2);
            int kb = 2 * (ln & 3);
            float f[4], fh[4];
#pragma unroll
            for (int q = 0; q < 4; q++) {
                int k = kb + (q >> 1) * 8 + (q & 1);
                f[q]  = wsl[k * 128 + nn];
                fh[q] = __half2float(__float2half_rn(f[q]));
            }
            int gi = ks * 512 + i;
            g_whf[sel][gi] = make_uint2(h2(f[0], f[1]), h2(f[2], f[3]));
            g_wlf[sel][gi] = make_uint2(h2(f[0] - fh[0], f[1] - fh[1]),
                                        h2(f[2] - fh[2], f[3] - fh[3]));
        }
        __threadfence();
        __syncthreads();
        if (tid == 0) {
            unsigned d = atomicAdd((unsigned*)&g_sync[0], 1u);
            if (d == 13u) { __threadfence(); sync[2] = 1u; }
        }
        __syncthreads();
    }

    // ======================= Phase B: node tiles ==========================
    const int n_node = nb_drug + nb_dis;
    for (int nt = bid; nt < n_node; nt += GRID) {
        char* xh = hsraw;
        char* xl = hsraw + NNB * XS_RS;
        __syncthreads();                       // hsraw free (frag build done)

        const bool is_drug = nt < nb_drug;
        const int  sel     = is_drug ? 0 : 1;
        const int  n       = is_drug ? n_drug : n_dis;
        const int  nbase   = (is_drug ? nt : nt - nb_drug) * NNB;
        const float* x   = is_drug ? xd : xs;
        __half*      outh = is_drug ? g_hd : g_he;

        for (int i = tid; i < NNB * 56; i += NTHR) {
            int row = i / 56;
            int p   = i - row * 56;
            int gn  = nbase + row;
            int k0  = 2 * p;
            float v0 = 0.0f, v1 = 0.0f;
            if (gn < n) {
                if (k0 < 100)     v0 = x[(long)gn * 100 + k0];
                if (k0 + 1 < 100) v1 = x[(long)gn * 100 + k0 + 1];
            }
            float h0 = __half2float(__float2half_rn(v0));
            float h1 = __half2float(__float2half_rn(v1));
            *(uint32_t*)(xh + row * XS_RS + 4 * p) = h2(v0, v1);
            *(uint32_t*)(xl + row * XS_RS + 4 * p) = h2(v0 - h0, v1 - h1);
        }

        if (tid == 0) { while (sync[2] == 0u) ; }   // frags ready?
        __syncthreads();
        __threadfence();

        const int g = lane >> 2;
        const int c = lane & 3;
        const int mt = warp & 3;
        const int nh = warp >> 2;
        const char* axh = xh + (mt * 16 + g) * XS_RS + 4 * c;
        const char* axl = xl + (mt * 16 + g) * XS_RS + 4 * c;
        const uint2* whf = g_whf[sel];
        const uint2* wlf = g_wlf[sel];

        float acc[8][4];
#pragma unroll
        for (int nb = 0; nb < 8; nb++)
#pragma unroll
            for (int q = 0; q < 4; q++) acc[nb][q] = 0.0f;

#pragma unroll
        for (int ks = 0; ks < 7; ks++) {
            uint32_t ah0 = *(const uint32_t*)(axh + 32 * ks);
            uint32_t ah1 = *(const uint32_t*)(axh + 32 * ks + 8 * XS_RS);
            uint32_t ah2 = *(const uint32_t*)(axh + 32 * ks + 16);
            uint32_t ah3 = *(const uint32_t*)(axh + 32 * ks + 8 * XS_RS + 16);
            uint32_t al0 = *(const uint32_t*)(axl + 32 * ks);
            uint32_t al1 = *(const uint32_t*)(axl + 32 * ks + 8 * XS_RS);
            uint32_t al2 = *(const uint32_t*)(axl + 32 * ks + 16);
            uint32_t al3 = *(const uint32_t*)(axl + 32 * ks + 8 * XS_RS + 16);
#pragma unroll
            for (int nb = 0; nb < 8; nb++) {
                int fi = (ks * 16 + nh * 8 + nb) * 32 + lane;
                uint2 bh = __ldg(&whf[fi]);
                uint2 bl = __ldg(&wlf[fi]);
                hmma16(acc[nb], ah0, ah1, ah2, ah3, bh.x, bh.y);
                hmma16(acc[nb], al0, al1, al2, al3, bh.x, bh.y);
                hmma16(acc[nb], ah0, ah1, ah2, ah3, bl.x, bl.y);
            }
        }

        int r0 = nbase + mt * 16 + g;
        int r1 = r0 + 8;
#pragma unroll
        for (int nb = 0; nb < 8; nb++) {
            int col = nh * 64 + nb * 8 + 2 * c;
            float bb0 = is_drug ? __ldg(&b1[col])     : 0.0f;
            float bb1 = is_drug ? __ldg(&b1[col + 1]) : 0.0f;
            if (r0 < n)
                *(uint32_t*)((char*)outh + (long)r0 * 256 + col * 2) =
                    h2(acc[nb][0] + bb0, acc[nb][1] + bb1);
            if (r1 < n)
                *(uint32_t*)((char*)outh + (long)r1 * 256 + col * 2) =
                    h2(acc[nb][2] + bb0, acc[nb][3] + bb1);
        }
        __threadfence();
        __syncthreads();
        if (tid == 0) {
            unsigned d = atomicAdd((unsigned*)&g_sync[1], 1u);
            if (d == (unsigned)(n_node - 1)) { __threadfence(); sync[3] = 1u; }
        }
    }

    // ======================= Phase C: edge MLP ============================
    const int g = lane >> 2;
    const int c = lane & 3;

    // register constants (overlap the node wait)
    float b2r[4][2];
#pragma unroll
    for (int nb = 0; nb < 4; nb++) {
        b2r[nb][0] = __ldg(&b2[8 * nb + 2 * c + 0]);
        b2r[nb][1] = __ldg(&b2[8 * nb + 2 * c + 1]);
    }
    uint32_t w3f[2][2][2];
#pragma unroll
    for (int ks3 = 0; ks3 < 2; ks3++)
#pragma unroll
        for (int nb3 = 0; nb3 < 2; nb3++) {
            int n  = 8 * nb3 + g;
            int kb = 16 * ks3 + 2 * c;
            w3f[ks3][nb3][0] = h2(__ldg(&W3[kb * 16 + n]),
                                  __ldg(&W3[(kb + 1) * 16 + n]));
            w3f[ks3][nb3][1] = h2(__ldg(&W3[(kb + 8) * 16 + n]),
                                  __ldg(&W3[(kb + 9) * 16 + n]));
        }
    float b3r[2][2], w4r[2][2];
#pragma unroll
    for (int o = 0; o < 2; o++) {
        b3r[o][0] = __ldg(&b3[8 * o + 2 * c + 0]);
        b3r[o][1] = __ldg(&b3[8 * o + 2 * c + 1]);
        w4r[o][0] = __ldg(&W4[8 * o + 2 * c + 0]);
        w4r[o][1] = __ldg(&W4[8 * o + 2 * c + 1]);
    }
    const float b4v = __ldg(&b4[0]);
    const __half2 c01 = __float2half2_rn(0.01f);

    if (tid == 0) { while (sync[3] == 0u) ; }   // node tables ready?
    __syncthreads();
    __threadfence();

    const int is64 = g_idx64;
    char* hw = hsraw + warp * 16 * HS_RS;
    const char* hdb = (const char*)g_hd;
    const char* heb = (const char*)g_he;

    const int half = lane >> 4;
    const int sub  = lane & 15;
    const uint32_t boff = (uint32_t)(sub << 4);

    for (int tile = bid; tile < n_tiles; tile += GRID) {
        const int ebase = tile * EPB + warp * 16;

        {
            int e  = ebase + (lane & 15);
            int ec = e < E ? e : (E - 1);
            long long pos = (lane < 16) ? (long long)ec : (long long)E + ec;
            int vi = (int)load_idx(ell, pos, is64);

#pragma unroll
            for (int t = 0; t < 8; t++) {
                int r = 2 * t + half;
                uint32_t i = (uint32_t)__shfl_sync(0xffffffffu, vi, r);
                uint32_t j = (uint32_t)__shfl_sync(0xffffffffu, vi, r + 16);
                const uint4 a = *(const uint4*)(hdb + (i << 8) + boff);
                const uint4 b = *(const uint4*)(heb + (j << 8) + boff);
                uint4 s;
                s.x = haddlrelu2(a.x, b.x, c01);
                s.y = haddlrelu2(a.y, b.y, c01);
                s.z = haddlrelu2(a.z, b.z, c01);
                s.w = haddlrelu2(a.w, b.w, c01);
                *(uint4*)(hw + r * HS_RS + boff) = s;
            }
        }
        __syncwarp();

        float acc[4][4];
#pragma unroll
        for (int nb = 0; nb < 4; nb++)
#pragma unroll
            for (int q = 0; q < 4; q++) acc[nb][q] = 0.0f;

        {
            const char* r0 = hw + g * HS_RS + 4 * c;
            const char* r1 = r0 + 8 * HS_RS;
#pragma unroll
            for (int ks = 0; ks < 8; ks++) {
                uint32_t a0 = *(const uint32_t*)(r0 + 32 * ks);
                uint32_t a1 = *(const uint32_t*)(r1 + 32 * ks);
                uint32_t a2 = *(const uint32_t*)(r0 + 32 * ks + 16);
                uint32_t a3 = *(const uint32_t*)(r1 + 32 * ks + 16);
#pragma unroll
                for (int nbp = 0; nbp < 2; nbp++) {
                    uint4 bb = wfr[(ks * 2 + nbp) * 32 + lane];
                    hmma16(acc[2 * nbp],     a0, a1, a2, a3, bb.x, bb.y);
                    hmma16(acc[2 * nbp + 1], a0, a1, a2, a3, bb.z, bb.w);
                }
            }
        }
        __syncwarp();

        float acc3[2][4];
#pragma unroll
        for (int o = 0; o < 2; o++)
#pragma unroll
            for (int q = 0; q < 4; q++) acc3[o][q] = 0.0f;

#pragma unroll
        for (int ks3 = 0; ks3 < 2; ks3++) {
            const int nbA = 2 * ks3;
            const int nbB = 2 * ks3 + 1;
            uint32_t a0 = h2(lrelu(acc[nbA][0] + b2r[nbA][0]),
                             lrelu(acc[nbA][1] + b2r[nbA][1]));
            uint32_t a1 = h2(lrelu(acc[nbA][2] + b2r[nbA][0]),
                             lrelu(acc[nbA][3] + b2r[nbA][1]));
            uint32_t a2 = h2(lrelu(acc[nbB][0] + b2r[nbB][0]),
                             lrelu(acc[nbB][1] + b2r[nbB][1]));
            uint32_t a3 = h2(lrelu(acc[nbB][2] + b2r[nbB][0]),
                             lrelu(acc[nbB][3] + b2r[nbB][1]));
#pragma unroll
            for (int nb3 = 0; nb3 < 2; nb3++)
                hmma16(acc3[nb3], a0, a1, a2, a3,
                       w3f[ks3][nb3][0], w3f[ks3][nb3][1]);
        }

        {
            float y0 = 0.0f, y1 = 0.0f;
#pragma unroll
            for (int o = 0; o < 2; o++) {
                y0 = fmaf(lrelu(acc3[o][0] + b3r[o][0]), w4r[o][0], y0);
                y0 = fmaf(lrelu(acc3[o][1] + b3r[o][1]), w4r[o][1], y0);
                y1 = fmaf(lrelu(acc3[o][2] + b3r[o][0]), w4r[o][0], y1);
                y1 = fmaf(lrelu(acc3[o][3] + b3r[o][1]), w4r[o][1], y1);
            }
            y0 += __shfl_xor_sync(0xffffffffu, y0, 1);
            y0 += __shfl_xor_sync(0xffffffffu, y0, 2);
            y1 += __shfl_xor_sync(0xffffffffu, y1, 1);
            y1 += __shfl_xor_sync(0xffffffffu, y1, 2);

            if (c == 0) {
                int e0 = ebase + g;
                if (e0 < E)     out[e0]     = y0 + b4v;
                if (e0 + 8 < E) out[e0 + 8] = y1 + b4v;
            }
        }
    }
}

// ---------------------------------------------------------------------------
extern "C" void kernel_launch(void* const* d_in, const int* in_sizes, int n_in,
                              void* d_out, int out_size) {
    const float* xd  = (const float*)d_in[0];
    const float* xs  = (const float*)d_in[1];
    const void*  ell = d_in[2];
    const float* W1  = (const float*)d_in[3];
    const float* b1  = (const float*)d_in[4];
    const float* W2  = (const float*)d_in[5];
    const float* b2  = (const float*)d_in[6];
    const float* W3  = (const float*)d_in[7];
    const float* b3  = (const float*)d_in[8];
    const float* W4  = (const float*)d_in[9];
    const float* b4  = (const float*)d_in[10];
    float* out = (float*)d_out;

    int n_drug = in_sizes[0] / 100;
    int n_dis  = in_sizes[1] / 100;
    int E      = in_sizes[2] / 2;
    int nb_drug = (n_drug + NNB - 1) / NNB;
    int nb_dis  = (n_dis  + NNB - 1) / NNB;
    int n_tiles = (E + EPB - 1) / EPB;

    void* sa = nullptr;
    cudaGetSymbolAddress(&sa, g_sync);
    cudaMemsetAsync(sa, 0, 4 * sizeof(unsigned));

    fused_kernel<<<GRID, NTHR>>>(xd, xs, ell, W1, b1, W2, b2, W3, b3, W4, b4,
                                 out, n_drug, n_dis, nb_drug, nb_dis,
                                 E, n_tiles);
}

// round 16
// speedup vs baseline: 1.0116x; 1.0116x over previous
#include <cuda_runtime.h>
#include <cuda_bf16.h>
#include <cuda_fp16.h>
#include <cstdint>

// ---------------------------------------------------------------------------
// Classifier: out[e] = MLP(concat(x_drug[i_e], x_disease[j_e]))
// Three kernels (R14 structure — fusion regressed and was reverted):
//  K0: W1 hi/lo fp16 fragment build, 14 blocks, smem-staged (once).
//  K1: layer-1 per-node GEMM on tensor cores, split fp16 (err ~1e-7),
//      fp16 node tables g_hd/g_he.
//  K2: persistent per-edge MLP: h = lrelu(hd[i]+he[j]) in half2 -> fp16 smem;
//      layer-2 (128->32) mma with W2 B-fragments REGISTER-RESIDENT (loaded
//      once per block, reused ~211 tiles); layer-3 mma (composing frags);
//      layer-4 dot + shfl reduce. launch_bounds(256,2), grid 296.
// ---------------------------------------------------------------------------

typedef unsigned long long ull;

#define MAX_NODES 16384
__device__ __half g_hd[MAX_NODES * 128];
__device__ __half g_he[MAX_NODES * 128];
__device__ int    g_idx64;   // 1 if edge index buffer is int64, 0 if int32

#define NFRAG (7 * 16 * 32)              // 3584 uint2 per set
__device__ uint2 g_whf[2][NFRAG];        // [0]=drug slice, [1]=disease slice
__device__ uint2 g_wlf[2][NFRAG];

__device__ __forceinline__ float lrelu(float v) {
    return v >= 0.0f ? v : 0.01f * v;
}
__device__ __forceinline__ uint32_t h2(float a, float b) {
    __half2 h = __floats2half2_rn(a, b);   // x(lo)=a, y(hi)=b
    return *(uint32_t*)&h;
}
// packed fp16 add + leaky-relu: lrelu(x) == max(x, 0.01*x) elementwise
__device__ __forceinline__ uint32_t haddlrelu2(uint32_t a, uint32_t b,
                                               __half2 c01) {
    __half2 s = __hadd2(*(__half2*)&a, *(__half2*)&b);
    __half2 r = __hmax2(s, __hmul2(s, c01));
    return *(uint32_t*)&r;
}
__device__ __forceinline__ long long load_idx(const void* ell, long long pos,
                                              int is64) {
    if (is64) return ((const long long*)ell)[pos];
    return (long long)((const int*)ell)[pos];
}

// m16n8k16 f16 MMA (row.col), fp32 accumulate in place
__device__ __forceinline__ void hmma16(float d[4], uint32_t a0, uint32_t a1,
                                       uint32_t a2, uint32_t a3,
                                       uint32_t b0, uint32_t b1) {
    asm volatile(
        "mma.sync.aligned.m16n8k16.row.col.f32.f16.f16.f32 "
        "{%0,%1,%2,%3}, {%4,%5,%6,%7}, {%8,%9}, {%0,%1,%2,%3};"
        : "+f"(d[0]), "+f"(d[1]), "+f"(d[2]), "+f"(d[3])
        : "r"(a0), "r"(a1), "r"(a2), "r"(a3), "r"(b0), "r"(b1));
}

// ---------------------------------------------------------------------------
// Kernel 0: one-time W1 hi/lo fragment build (14 blocks, smem-staged).
// Block 0 also detects the edge-index dtype (JAX w/o x64 -> int32).
// ---------------------------------------------------------------------------
__global__ void w1_frag_prep(const float* __restrict__ W1,
                             const long long* __restrict__ ell) {
    __shared__ float wsl[16 * 128];

    const int tid = threadIdx.x;
    const int sel = blockIdx.x / 7;
    const int ks  = blockIdx.x % 7;

    if (blockIdx.x == 0 && tid == 0) {
        int ok64 = 1;
#pragma unroll
        for (int t = 0; t < 8; t++) {
            long long v = ell[t];
            if (v < 0 || v >= 1000000) ok64 = 0;
        }
        g_idx64 = ok64;
    }

    const float* w = W1 + sel * 100 * 128 + 16 * ks * 128;
    const int krows = (100 - 16 * ks) < 16 ? (100 - 16 * ks) : 16;

    for (int i = tid; i < 16 * 32; i += 256) {
        float4 v = make_float4(0.f, 0.f, 0.f, 0.f);
        if ((i >> 5) < krows) v = ((const float4*)w)[i];
        ((float4*)wsl)[i] = v;
    }
    __syncthreads();

    for (int i = tid; i < 512; i += 256) {
        int ln = i & 31;
        int nb = i >> 5;
        int nn = 8 * nb + (ln >> 2);
        int kb = 2 * (ln & 3);
        float f[4], fh[4];
#pragma unroll
        for (int q = 0; q < 4; q++) {
            int k = kb + (q >> 1) * 8 + (q & 1);
            f[q]  = wsl[k * 128 + nn];
            fh[q] = __half2float(__float2half_rn(f[q]));
        }
        int gi = ks * 512 + i;
        g_whf[sel][gi] = make_uint2(h2(f[0], f[1]), h2(f[2], f[3]));
        g_wlf[sel][gi] = make_uint2(h2(f[0] - fh[0], f[1] - fh[1]),
                                    h2(f[2] - fh[2], f[3] - fh[3]));
    }
}

// ---------------------------------------------------------------------------
// Kernel 1: layer-1 precompute on tensor cores. 64 nodes/block, 256 threads.
// ---------------------------------------------------------------------------
#define NNB   64
#define XS_RS 240                              // 112 halves = 224B + 16 pad

__global__ void __launch_bounds__(256, 4)
node_precompute(const float* __restrict__ xd,
                const float* __restrict__ xs,
                const float* __restrict__ b1,
                int n_drug, int n_dis, int nb_drug) {
    __shared__ char xh[NNB * XS_RS];
    __shared__ char xl[NNB * XS_RS];

    const int tid = threadIdx.x;
    const int bid = blockIdx.x;

    const bool is_drug = bid < nb_drug;
    const int  sel     = is_drug ? 0 : 1;
    const int  n       = is_drug ? n_drug : n_dis;
    const int  nbase   = (is_drug ? bid : bid - nb_drug) * NNB;
    const float* x   = is_drug ? xd : xs;
    __half*      out = is_drug ? g_hd : g_he;

    for (int i = tid; i < NNB * 56; i += 256) {
        int row = i / 56;
        int p   = i - row * 56;
        int gn  = nbase + row;
        int k0  = 2 * p;
        float v0 = 0.0f, v1 = 0.0f;
        if (gn < n) {
            if (k0 < 100)     v0 = x[(long)gn * 100 + k0];
            if (k0 + 1 < 100) v1 = x[(long)gn * 100 + k0 + 1];
        }
        float h0 = __half2float(__float2half_rn(v0));
        float h1 = __half2float(__float2half_rn(v1));
        *(uint32_t*)(xh + row * XS_RS + 4 * p) = h2(v0, v1);
        *(uint32_t*)(xl + row * XS_RS + 4 * p) = h2(v0 - h0, v1 - h1);
    }
    __syncthreads();

    const int warp = tid >> 5;
    const int lane = tid & 31;
    const int g = lane >> 2;
    const int c = lane & 3;
    const int mt = warp & 3;
    const int nh = warp >> 2;

    const char* axh = xh + (mt * 16 + g) * XS_RS + 4 * c;
    const char* axl = xl + (mt * 16 + g) * XS_RS + 4 * c;
    const uint2* whf = g_whf[sel];
    const uint2* wlf = g_wlf[sel];

    float acc[8][4];
#pragma unroll
    for (int nb = 0; nb < 8; nb++)
#pragma unroll
        for (int q = 0; q < 4; q++) acc[nb][q] = 0.0f;

#pragma unroll
    for (int ks = 0; ks < 7; ks++) {
        uint32_t ah0 = *(const uint32_t*)(axh + 32 * ks);
        uint32_t ah1 = *(const uint32_t*)(axh + 32 * ks + 8 * XS_RS);
        uint32_t ah2 = *(const uint32_t*)(axh + 32 * ks + 16);
        uint32_t ah3 = *(const uint32_t*)(axh + 32 * ks + 8 * XS_RS + 16);
        uint32_t al0 = *(const uint32_t*)(axl + 32 * ks);
        uint32_t al1 = *(const uint32_t*)(axl + 32 * ks + 8 * XS_RS);
        uint32_t al2 = *(const uint32_t*)(axl + 32 * ks + 16);
        uint32_t al3 = *(const uint32_t*)(axl + 32 * ks + 8 * XS_RS + 16);
#pragma unroll
        for (int nb = 0; nb < 8; nb++) {
            int fi = (ks * 16 + nh * 8 + nb) * 32 + lane;
            uint2 bh = __ldg(&whf[fi]);
            uint2 bl = __ldg(&wlf[fi]);
            hmma16(acc[nb], ah0, ah1, ah2, ah3, bh.x, bh.y);
            hmma16(acc[nb], al0, al1, al2, al3, bh.x, bh.y);
            hmma16(acc[nb], ah0, ah1, ah2, ah3, bl.x, bl.y);
        }
    }

    int r0 = nbase + mt * 16 + g;
    int r1 = r0 + 8;
#pragma unroll
    for (int nb = 0; nb < 8; nb++) {
        int col = nh * 64 + nb * 8 + 2 * c;
        float bb0 = is_drug ? __ldg(&b1[col])     : 0.0f;
        float bb1 = is_drug ? __ldg(&b1[col + 1]) : 0.0f;
        if (r0 < n)
            *(uint32_t*)((char*)out + (long)r0 * 256 + col * 2) =
                h2(acc[nb][0] + bb0, acc[nb][1] + bb1);
        if (r1 < n)
            *(uint32_t*)((char*)out + (long)r1 * 256 + col * 2) =
                h2(acc[nb][2] + bb0, acc[nb][3] + bb1);
    }
}

// ---------------------------------------------------------------------------
// Kernel 2: persistent per-edge MLP; W2 B-frags register-resident.
// Block = 256 threads (8 warps), tile = 128 edges, warp owns 16 edges.
// ---------------------------------------------------------------------------
#define EPB   128
#define NTHR  256
#define HS_RS 272                       // bytes per hs row (256 + 16 pad)

__global__ void __launch_bounds__(NTHR, 2)
edge_mlp_kernel(const void* __restrict__ ell,
                const float* __restrict__ W2, const float* __restrict__ b2,
                const float* __restrict__ W3, const float* __restrict__ b3,
                const float* __restrict__ W4, const float* __restrict__ b4,
                float* __restrict__ out, int E, int n_tiles) {
    __shared__ char  hsraw[8 * 16 * HS_RS];   // 34816 B
    __shared__ uint4 wfr[8 * 2 * 32];         // W2 frag staging (8 KB)

    const int tid  = threadIdx.x;
    const int warp = tid >> 5;
    const int lane = tid & 31;
    const int is64 = g_idx64;

    // ---- stage W2 fp16 B-fragments, then lift to registers ----
    for (int idx = tid; idx < 512; idx += NTHR) {
        int ln  = idx & 31;
        int nbp = (idx >> 5) & 1;
        int ks  = idx >> 6;
        int n0  = 16 * nbp + (ln >> 2);
        int n1  = n0 + 8;
        int kb  = 16 * ks + 2 * (ln & 3);
        uint4 b;
        b.x = h2(W2[kb * 32 + n0],       W2[(kb + 1) * 32 + n0]);
        b.y = h2(W2[(kb + 8) * 32 + n0], W2[(kb + 9) * 32 + n0]);
        b.z = h2(W2[kb * 32 + n1],       W2[(kb + 1) * 32 + n1]);
        b.w = h2(W2[(kb + 8) * 32 + n1], W2[(kb + 9) * 32 + n1]);
        wfr[idx] = b;
    }
    __syncthreads();

    uint4 breg[8][2];                    // 64 registers, loop-invariant
#pragma unroll
    for (int ks = 0; ks < 8; ks++)
#pragma unroll
        for (int nbp = 0; nbp < 2; nbp++)
            breg[ks][nbp] = wfr[(ks * 2 + nbp) * 32 + lane];

    const int g = lane >> 2;
    const int c = lane & 3;

    float b2r[4][2];
#pragma unroll
    for (int nb = 0; nb < 4; nb++) {
        b2r[nb][0] = __ldg(&b2[8 * nb + 2 * c + 0]);
        b2r[nb][1] = __ldg(&b2[8 * nb + 2 * c + 1]);
    }
    uint32_t w3f[2][2][2];
#pragma unroll
    for (int ks3 = 0; ks3 < 2; ks3++)
#pragma unroll
        for (int nb3 = 0; nb3 < 2; nb3++) {
            int n  = 8 * nb3 + g;
            int kb = 16 * ks3 + 2 * c;
            w3f[ks3][nb3][0] = h2(__ldg(&W3[kb * 16 + n]),
                                  __ldg(&W3[(kb + 1) * 16 + n]));
            w3f[ks3][nb3][1] = h2(__ldg(&W3[(kb + 8) * 16 + n]),
                                  __ldg(&W3[(kb + 9) * 16 + n]));
        }
    float b3r[2][2], w4r[2][2];
#pragma unroll
    for (int o = 0; o < 2; o++) {
        b3r[o][0] = __ldg(&b3[8 * o + 2 * c + 0]);
        b3r[o][1] = __ldg(&b3[8 * o + 2 * c + 1]);
        w4r[o][0] = __ldg(&W4[8 * o + 2 * c + 0]);
        w4r[o][1] = __ldg(&W4[8 * o + 2 * c + 1]);
    }
    const float b4v = __ldg(&b4[0]);
    const __half2 c01 = __float2half2_rn(0.01f);

    char* hw = hsraw + warp * 16 * HS_RS;
    const char* hdb = (const char*)g_hd;
    const char* heb = (const char*)g_he;

    const int half = lane >> 4;
    const int sub  = lane & 15;
    const uint32_t boff = (uint32_t)(sub << 4);

    for (int tile = blockIdx.x; tile < n_tiles; tile += gridDim.x) {
        const int ebase = tile * EPB + warp * 16;

        // ---- phase 1: gather + half2 combine+lrelu -> fp16 smem ----
        {
            int e  = ebase + (lane & 15);
            int ec = e < E ? e : (E - 1);
            long long pos = (lane < 16) ? (long long)ec : (long long)E + ec;
            int vi = (int)load_idx(ell, pos, is64);

#pragma unroll
            for (int t = 0; t < 8; t++) {
                int r = 2 * t + half;
                uint32_t i = (uint32_t)__shfl_sync(0xffffffffu, vi, r);
                uint32_t j = (uint32_t)__shfl_sync(0xffffffffu, vi, r + 16);
                const uint4 a = *(const uint4*)(hdb + (i << 8) + boff);
                const uint4 b = *(const uint4*)(heb + (j << 8) + boff);
                uint4 s;
                s.x = haddlrelu2(a.x, b.x, c01);
                s.y = haddlrelu2(a.y, b.y, c01);
                s.z = haddlrelu2(a.z, b.z, c01);
                s.w = haddlrelu2(a.w, b.w, c01);
                *(uint4*)(hw + r * HS_RS + boff) = s;
            }
        }
        __syncwarp();

        // ---- phase 2: layer-2 mma, B from registers ----
        float acc[4][4];
#pragma unroll
        for (int nb = 0; nb < 4; nb++)
#pragma unroll
            for (int q = 0; q < 4; q++) acc[nb][q] = 0.0f;

        {
            const char* r0 = hw + g * HS_RS + 4 * c;
            const char* r1 = r0 + 8 * HS_RS;
#pragma unroll
            for (int ks = 0; ks < 8; ks++) {
                uint32_t a0 = *(const uint32_t*)(r0 + 32 * ks);
                uint32_t a1 = *(const uint32_t*)(r1 + 32 * ks);
                uint32_t a2 = *(const uint32_t*)(r0 + 32 * ks + 16);
                uint32_t a3 = *(const uint32_t*)(r1 + 32 * ks + 16);
                hmma16(acc[0], a0, a1, a2, a3, breg[ks][0].x, breg[ks][0].y);
                hmma16(acc[1], a0, a1, a2, a3, breg[ks][0].z, breg[ks][0].w);
                hmma16(acc[2], a0, a1, a2, a3, breg[ks][1].x, breg[ks][1].y);
                hmma16(acc[3], a0, a1, a2, a3, breg[ks][1].z, breg[ks][1].w);
            }
        }
        __syncwarp();    // hs consumed; safe to rewrite next tile

        // ---- phase 3: layer-3 mma — layer-2 D frag IS layer-3 A frag ----
        float acc3[2][4];
#pragma unroll
        for (int o = 0; o < 2; o++)
#pragma unroll
            for (int q = 0; q < 4; q++) acc3[o][q] = 0.0f;

#pragma unroll
        for (int ks3 = 0; ks3 < 2; ks3++) {
            const int nbA = 2 * ks3;
            const int nbB = 2 * ks3 + 1;
            uint32_t a0 = h2(lrelu(acc[nbA][0] + b2r[nbA][0]),
                             lrelu(acc[nbA][1] + b2r[nbA][1]));
            uint32_t a1 = h2(lrelu(acc[nbA][2] + b2r[nbA][0]),
                             lrelu(acc[nbA][3] + b2r[nbA][1]));
            uint32_t a2 = h2(lrelu(acc[nbB][0] + b2r[nbB][0]),
                             lrelu(acc[nbB][1] + b2r[nbB][1]));
            uint32_t a3 = h2(lrelu(acc[nbB][2] + b2r[nbB][0]),
                             lrelu(acc[nbB][3] + b2r[nbB][1]));
#pragma unroll
            for (int nb3 = 0; nb3 < 2; nb3++)
                hmma16(acc3[nb3], a0, a1, a2, a3,
                       w3f[ks3][nb3][0], w3f[ks3][nb3][1]);
        }

        // ---- phase 4: bias+leaky, dot W4, shfl-reduce over c, store ----
        {
            float y0 = 0.0f, y1 = 0.0f;
#pragma unroll
            for (int o = 0; o < 2; o++) {
                y0 = fmaf(lrelu(acc3[o][0] + b3r[o][0]), w4r[o][0], y0);
                y0 = fmaf(lrelu(acc3[o][1] + b3r[o][1]), w4r[o][1], y0);
                y1 = fmaf(lrelu(acc3[o][2] + b3r[o][0]), w4r[o][0], y1);
                y1 = fmaf(lrelu(acc3[o][3] + b3r[o][1]), w4r[o][1], y1);
            }
            y0 += __shfl_xor_sync(0xffffffffu, y0, 1);
            y0 += __shfl_xor_sync(0xffffffffu, y0, 2);
            y1 += __shfl_xor_sync(0xffffffffu, y1, 1);
            y1 += __shfl_xor_sync(0xffffffffu, y1, 2);

            if (c == 0) {
                int e0 = ebase + g;
                if (e0 < E)     out[e0]     = y0 + b4v;
                if (e0 + 8 < E) out[e0 + 8] = y1 + b4v;
            }
        }
    }
}

// ---------------------------------------------------------------------------
extern "C" void kernel_launch(void* const* d_in, const int* in_sizes, int n_in,
                              void* d_out, int out_size) {
    const float* xd  = (const float*)d_in[0];
    const float* xs  = (const float*)d_in[1];
    const void*  ell = d_in[2];
    const float* W1  = (const float*)d_in[3];
    const float* b1  = (const float*)d_in[4];
    const float* W2  = (const float*)d_in[5];
    const float* b2  = (const float*)d_in[6];
    const float* W3  = (const float*)d_in[7];
    const float* b3  = (const float*)d_in[8];
    const float* W4  = (const float*)d_in[9];
    const float* b4  = (const float*)d_in[10];
    float* out = (float*)d_out;

    int n_drug = in_sizes[0] / 100;
    int n_dis  = in_sizes[1] / 100;
    int E      = in_sizes[2] / 2;

    w1_frag_prep<<<14, 256>>>(W1, (const long long*)ell);

    int nb_drug = (n_drug + NNB - 1) / NNB;
    int nb_dis  = (n_dis  + NNB - 1) / NNB;
    node_precompute<<<nb_drug + nb_dis, 256>>>(xd, xs, b1,
                                               n_drug, n_dis, nb_drug);

    int n_tiles = (E + EPB - 1) / EPB;
    int grid = 2 * 148;
    if (grid > n_tiles) grid = n_tiles;
    edge_mlp_kernel<<<grid, NTHR>>>(ell, W2, b2, W3, b3, W4, b4,
                                    out, E, n_tiles);
}

// round 17
// speedup vs baseline: 1.0262x; 1.0144x over previous
#include <cuda_runtime.h>
#include <cuda_bf16.h>
#include <cuda_fp16.h>
#include <cstdint>

// ---------------------------------------------------------------------------
// Classifier: out[e] = MLP(concat(x_drug[i_e], x_disease[j_e]))
// Two kernels:
//  K1 (merged): blocks 0-13 build W1 hi/lo fp16 fragments (split precision);
//      blocks 14.. run layer-1 per-node GEMM on tensor cores
//      (x=xh+xl, W1=Wh+Wl; xh@Wh+xl@Wh+xh@Wl in fp32 -> err ~1e-7),
//      overlapping x-staging with the frag build (flag poll). fp16 tables.
//  K2: persistent per-edge MLP (exact R14 winner): h = lrelu(hd[i]+he[j])
//      in half2 -> fp16 smem; layers 2/3 on mma.m16n8k16.f16 (fp32 accum)
//      with composing fragment layouts; layer-4 dot + shfl reduce.
// ---------------------------------------------------------------------------

typedef unsigned long long ull;

#define MAX_NODES 16384
__device__ __half g_hd[MAX_NODES * 128];
__device__ __half g_he[MAX_NODES * 128];
__device__ int    g_idx64;   // 1 if edge index buffer is int64, 0 if int32

#define NFRAG (7 * 16 * 32)              // 3584 uint2 per set
__device__ uint2 g_whf[2][NFRAG];        // [0]=drug slice, [1]=disease slice
__device__ uint2 g_wlf[2][NFRAG];
__device__ unsigned g_sync[2];           // [0]=frag count, [1]=frag flag

__device__ __forceinline__ float lrelu(float v) {
    return v >= 0.0f ? v : 0.01f * v;
}
__device__ __forceinline__ uint32_t h2(float a, float b) {
    __half2 h = __floats2half2_rn(a, b);   // x(lo)=a, y(hi)=b
    return *(uint32_t*)&h;
}
// packed fp16 add + leaky-relu: lrelu(x) == max(x, 0.01*x) elementwise
__device__ __forceinline__ uint32_t haddlrelu2(uint32_t a, uint32_t b,
                                               __half2 c01) {
    __half2 s = __hadd2(*(__half2*)&a, *(__half2*)&b);
    __half2 r = __hmax2(s, __hmul2(s, c01));
    return *(uint32_t*)&r;
}
__device__ __forceinline__ long long load_idx(const void* ell, long long pos,
                                              int is64) {
    if (is64) return ((const long long*)ell)[pos];
    return (long long)((const int*)ell)[pos];
}

// m16n8k16 f16 MMA (row.col), fp32 accumulate in place
__device__ __forceinline__ void hmma16(float d[4], uint32_t a0, uint32_t a1,
                                       uint32_t a2, uint32_t a3,
                                       uint32_t b0, uint32_t b1) {
    asm volatile(
        "mma.sync.aligned.m16n8k16.row.col.f32.f16.f16.f32 "
        "{%0,%1,%2,%3}, {%4,%5,%6,%7}, {%8,%9}, {%0,%1,%2,%3};"
        : "+f"(d[0]), "+f"(d[1]), "+f"(d[2]), "+f"(d[3])
        : "r"(a0), "r"(a1), "r"(a2), "r"(a3), "r"(b0), "r"(b1));
}

// ---------------------------------------------------------------------------
// Kernel 1 (merged): W1 frag build (blocks 0-13) + layer-1 node GEMM.
// grid = 14 + n_node blocks, 256 threads, occ 4 (single wave, no deadlock).
// ---------------------------------------------------------------------------
#define NNB   64
#define XS_RS 240                              // 112 halves = 224B + 16 pad

__global__ void __launch_bounds__(256, 4)
node_precompute(const float* __restrict__ xd,
                const float* __restrict__ xs,
                const float* __restrict__ W1,
                const float* __restrict__ b1,
                const long long* __restrict__ ell,
                int n_drug, int n_dis, int nb_drug) {
    __shared__ char xh[NNB * XS_RS];           // aliased as frag stage (8 KB)
    __shared__ char xl[NNB * XS_RS];

    const int tid = threadIdx.x;
    const int bid = blockIdx.x;
    volatile unsigned* sync = g_sync;

    // ======== blocks 0-13: W1 hi/lo fragment build, then exit ========
    if (bid < 14) {
        float* wsl = (float*)xh;               // 16*128 floats = 8 KB
        const int sel = bid / 7;
        const int ks  = bid % 7;

        if (bid == 0 && tid == 0) {
            int ok64 = 1;
#pragma unroll
            for (int t = 0; t < 8; t++) {
                long long v = ell[t];
                if (v < 0 || v >= 1000000) ok64 = 0;
            }
            g_idx64 = ok64;
        }

        const float* w = W1 + sel * 100 * 128 + 16 * ks * 128;
        const int krows = (100 - 16 * ks) < 16 ? (100 - 16 * ks) : 16;

        for (int i = tid; i < 16 * 32; i += 256) {
            float4 v = make_float4(0.f, 0.f, 0.f, 0.f);
            if ((i >> 5) < krows) v = ((const float4*)w)[i];
            ((float4*)wsl)[i] = v;
        }
        __syncthreads();

        for (int i = tid; i < 512; i += 256) {
            int ln = i & 31;
            int nb = i >> 5;
            int nn = 8 * nb + (ln >> 2);
            int kb = 2 * (ln & 3);
            float f[4], fh[4];
#pragma unroll
            for (int q = 0; q < 4; q++) {
                int k = kb + (q >> 1) * 8 + (q & 1);
                f[q]  = wsl[k * 128 + nn];
                fh[q] = __half2float(__float2half_rn(f[q]));
            }
            int gi = ks * 512 + i;
            g_whf[sel][gi] = make_uint2(h2(f[0], f[1]), h2(f[2], f[3]));
            g_wlf[sel][gi] = make_uint2(h2(f[0] - fh[0], f[1] - fh[1]),
                                        h2(f[2] - fh[2], f[3] - fh[3]));
        }
        __threadfence();
        __syncthreads();
        if (tid == 0) {
            unsigned d = atomicAdd(&g_sync[0], 1u);
            if (d == 13u) { __threadfence(); sync[1] = 1u; }
        }
        return;
    }

    // ======== blocks 14..: node tiles (x-staging overlaps frag build) ====
    const int nt = bid - 14;
    const bool is_drug = nt < nb_drug;
    const int  sel     = is_drug ? 0 : 1;
    const int  n       = is_drug ? n_drug : n_dis;
    const int  nbase   = (is_drug ? nt : nt - nb_drug) * NNB;
    const float* x   = is_drug ? xd : xs;
    __half*      out = is_drug ? g_hd : g_he;

    for (int i = tid; i < NNB * 56; i += 256) {
        int row = i / 56;
        int p   = i - row * 56;
        int gn  = nbase + row;
        int k0  = 2 * p;
        float v0 = 0.0f, v1 = 0.0f;
        if (gn < n) {
            if (k0 < 100)     v0 = x[(long)gn * 100 + k0];
            if (k0 + 1 < 100) v1 = x[(long)gn * 100 + k0 + 1];
        }
        float h0 = __half2float(__float2half_rn(v0));
        float h1 = __half2float(__float2half_rn(v1));
        *(uint32_t*)(xh + row * XS_RS + 4 * p) = h2(v0, v1);
        *(uint32_t*)(xl + row * XS_RS + 4 * p) = h2(v0 - h0, v1 - h1);
    }

    if (tid == 0) { while (sync[1] == 0u) ; }   // frags ready?
    __syncthreads();

    const int warp = tid >> 5;
    const int lane = tid & 31;
    const int g = lane >> 2;
    const int c = lane & 3;
    const int mt = warp & 3;
    const int nh = warp >> 2;

    const char* axh = xh + (mt * 16 + g) * XS_RS + 4 * c;
    const char* axl = xl + (mt * 16 + g) * XS_RS + 4 * c;
    const uint2* whf = g_whf[sel];
    const uint2* wlf = g_wlf[sel];

    float acc[8][4];
#pragma unroll
    for (int nb = 0; nb < 8; nb++)
#pragma unroll
        for (int q = 0; q < 4; q++) acc[nb][q] = 0.0f;

#pragma unroll
    for (int ks = 0; ks < 7; ks++) {
        uint32_t ah0 = *(const uint32_t*)(axh + 32 * ks);
        uint32_t ah1 = *(const uint32_t*)(axh + 32 * ks + 8 * XS_RS);
        uint32_t ah2 = *(const uint32_t*)(axh + 32 * ks + 16);
        uint32_t ah3 = *(const uint32_t*)(axh + 32 * ks + 8 * XS_RS + 16);
        uint32_t al0 = *(const uint32_t*)(axl + 32 * ks);
        uint32_t al1 = *(const uint32_t*)(axl + 32 * ks + 8 * XS_RS);
        uint32_t al2 = *(const uint32_t*)(axl + 32 * ks + 16);
        uint32_t al3 = *(const uint32_t*)(axl + 32 * ks + 8 * XS_RS + 16);
#pragma unroll
        for (int nb = 0; nb < 8; nb++) {
            int fi = (ks * 16 + nh * 8 + nb) * 32 + lane;
            uint2 bh = __ldg(&whf[fi]);
            uint2 bl = __ldg(&wlf[fi]);
            hmma16(acc[nb], ah0, ah1, ah2, ah3, bh.x, bh.y);
            hmma16(acc[nb], al0, al1, al2, al3, bh.x, bh.y);
            hmma16(acc[nb], ah0, ah1, ah2, ah3, bl.x, bl.y);
        }
    }

    int r0 = nbase + mt * 16 + g;
    int r1 = r0 + 8;
#pragma unroll
    for (int nb = 0; nb < 8; nb++) {
        int col = nh * 64 + nb * 8 + 2 * c;
        float bb0 = is_drug ? __ldg(&b1[col])     : 0.0f;
        float bb1 = is_drug ? __ldg(&b1[col + 1]) : 0.0f;
        if (r0 < n)
            *(uint32_t*)((char*)out + (long)r0 * 256 + col * 2) =
                h2(acc[nb][0] + bb0, acc[nb][1] + bb1);
        if (r1 < n)
            *(uint32_t*)((char*)out + (long)r1 * 256 + col * 2) =
                h2(acc[nb][2] + bb0, acc[nb][3] + bb1);
    }
}

// ---------------------------------------------------------------------------
// Kernel 2: persistent per-edge MLP (EXACT R14 winner — frozen).
// Block = 256 threads (8 warps), tile = 128 edges, warp owns 16 edges.
// ---------------------------------------------------------------------------
#define EPB   128
#define NTHR  256
#define HS_RS 272                       // bytes per hs row (256 + 16 pad)

__global__ void __launch_bounds__(NTHR, 3)
edge_mlp_kernel(const void* __restrict__ ell,
                const float* __restrict__ W2, const float* __restrict__ b2,
                const float* __restrict__ W3, const float* __restrict__ b3,
                const float* __restrict__ W4, const float* __restrict__ b4,
                float* __restrict__ out, int E, int n_tiles) {
    __shared__ char  hsraw[8 * 16 * HS_RS];   // 34816 B
    __shared__ uint4 wfr[8 * 2 * 32];         // W2 frags: [ks8][nbp2][lane]

    const int tid  = threadIdx.x;
    const int warp = tid >> 5;
    const int lane = tid & 31;
    const int is64 = g_idx64;

    for (int idx = tid; idx < 512; idx += NTHR) {
        int ln  = idx & 31;
        int nbp = (idx >> 5) & 1;
        int ks  = idx >> 6;
        int n0  = 16 * nbp + (ln >> 2);
        int n1  = n0 + 8;
        int kb  = 16 * ks + 2 * (ln & 3);
        uint4 b;
        b.x = h2(W2[kb * 32 + n0],       W2[(kb + 1) * 32 + n0]);
        b.y = h2(W2[(kb + 8) * 32 + n0], W2[(kb + 9) * 32 + n0]);
        b.z = h2(W2[kb * 32 + n1],       W2[(kb + 1) * 32 + n1]);
        b.w = h2(W2[(kb + 8) * 32 + n1], W2[(kb + 9) * 32 + n1]);
        wfr[idx] = b;
    }
    __syncthreads();

    const int g = lane >> 2;
    const int c = lane & 3;

    float b2r[4][2];
#pragma unroll
    for (int nb = 0; nb < 4; nb++) {
        b2r[nb][0] = __ldg(&b2[8 * nb + 2 * c + 0]);
        b2r[nb][1] = __ldg(&b2[8 * nb + 2 * c + 1]);
    }
    uint32_t w3f[2][2][2];
#pragma unroll
    for (int ks3 = 0; ks3 < 2; ks3++)
#pragma unroll
        for (int nb3 = 0; nb3 < 2; nb3++) {
            int n  = 8 * nb3 + g;
            int kb = 16 * ks3 + 2 * c;
            w3f[ks3][nb3][0] = h2(__ldg(&W3[kb * 16 + n]),
                                  __ldg(&W3[(kb + 1) * 16 + n]));
            w3f[ks3][nb3][1] = h2(__ldg(&W3[(kb + 8) * 16 + n]),
                                  __ldg(&W3[(kb + 9) * 16 + n]));
        }
    float b3r[2][2], w4r[2][2];
#pragma unroll
    for (int o = 0; o < 2; o++) {
        b3r[o][0] = __ldg(&b3[8 * o + 2 * c + 0]);
        b3r[o][1] = __ldg(&b3[8 * o + 2 * c + 1]);
        w4r[o][0] = __ldg(&W4[8 * o + 2 * c + 0]);
        w4r[o][1] = __ldg(&W4[8 * o + 2 * c + 1]);
    }
    const float b4v = __ldg(&b4[0]);
    const __half2 c01 = __float2half2_rn(0.01f);

    char* hw = hsraw + warp * 16 * HS_RS;
    const char* hdb = (const char*)g_hd;
    const char* heb = (const char*)g_he;

    const int half = lane >> 4;
    const int sub  = lane & 15;
    const uint32_t boff = (uint32_t)(sub << 4);

    for (int tile = blockIdx.x; tile < n_tiles; tile += gridDim.x) {
        const int ebase = tile * EPB + warp * 16;

        {
            int e  = ebase + (lane & 15);
            int ec = e < E ? e : (E - 1);
            long long pos = (lane < 16) ? (long long)ec : (long long)E + ec;
            int vi = (int)load_idx(ell, pos, is64);

#pragma unroll
            for (int t = 0; t < 8; t++) {
                int r = 2 * t + half;
                uint32_t i = (uint32_t)__shfl_sync(0xffffffffu, vi, r);
                uint32_t j = (uint32_t)__shfl_sync(0xffffffffu, vi, r + 16);
                const uint4 a = *(const uint4*)(hdb + (i << 8) + boff);
                const uint4 b = *(const uint4*)(heb + (j << 8) + boff);
                uint4 s;
                s.x = haddlrelu2(a.x, b.x, c01);
                s.y = haddlrelu2(a.y, b.y, c01);
                s.z = haddlrelu2(a.z, b.z, c01);
                s.w = haddlrelu2(a.w, b.w, c01);
                *(uint4*)(hw + r * HS_RS + boff) = s;
            }
        }
        __syncwarp();

        float acc[4][4];
#pragma unroll
        for (int nb = 0; nb < 4; nb++)
#pragma unroll
            for (int q = 0; q < 4; q++) acc[nb][q] = 0.0f;

        {
            const char* r0 = hw + g * HS_RS + 4 * c;
            const char* r1 = r0 + 8 * HS_RS;
#pragma unroll
            for (int ks = 0; ks < 8; ks++) {
                uint32_t a0 = *(const uint32_t*)(r0 + 32 * ks);
                uint32_t a1 = *(const uint32_t*)(r1 + 32 * ks);
                uint32_t a2 = *(const uint32_t*)(r0 + 32 * ks + 16);
                uint32_t a3 = *(const uint32_t*)(r1 + 32 * ks + 16);
#pragma unroll
                for (int nbp = 0; nbp < 2; nbp++) {
                    uint4 bb = wfr[(ks * 2 + nbp) * 32 + lane];
                    hmma16(acc[2 * nbp],     a0, a1, a2, a3, bb.x, bb.y);
                    hmma16(acc[2 * nbp + 1], a0, a1, a2, a3, bb.z, bb.w);
                }
            }
        }
        __syncwarp();

        float acc3[2][4];
#pragma unroll
        for (int o = 0; o < 2; o++)
#pragma unroll
            for (int q = 0; q < 4; q++) acc3[o][q] = 0.0f;

#pragma unroll
        for (int ks3 = 0; ks3 < 2; ks3++) {
            const int nbA = 2 * ks3;
            const int nbB = 2 * ks3 + 1;
            uint32_t a0 = h2(lrelu(acc[nbA][0] + b2r[nbA][0]),
                             lrelu(acc[nbA][1] + b2r[nbA][1]));
            uint32_t a1 = h2(lrelu(acc[nbA][2] + b2r[nbA][0]),
                             lrelu(acc[nbA][3] + b2r[nbA][1]));
            uint32_t a2 = h2(lrelu(acc[nbB][0] + b2r[nbB][0]),
                             lrelu(acc[nbB][1] + b2r[nbB][1]));
            uint32_t a3 = h2(lrelu(acc[nbB][2] + b2r[nbB][0]),
                             lrelu(acc[nbB][3] + b2r[nbB][1]));
#pragma unroll
            for (int nb3 = 0; nb3 < 2; nb3++)
                hmma16(acc3[nb3], a0, a1, a2, a3,
                       w3f[ks3][nb3][0], w3f[ks3][nb3][1]);
        }

        {
            float y0 = 0.0f, y1 = 0.0f;
#pragma unroll
            for (int o = 0; o < 2; o++) {
                y0 = fmaf(lrelu(acc3[o][0] + b3r[o][0]), w4r[o][0], y0);
                y0 = fmaf(lrelu(acc3[o][1] + b3r[o][1]), w4r[o][1], y0);
                y1 = fmaf(lrelu(acc3[o][2] + b3r[o][0]), w4r[o][0], y1);
                y1 = fmaf(lrelu(acc3[o][3] + b3r[o][1]), w4r[o][1], y1);
            }
            y0 += __shfl_xor_sync(0xffffffffu, y0, 1);
            y0 += __shfl_xor_sync(0xffffffffu, y0, 2);
            y1 += __shfl_xor_sync(0xffffffffu, y1, 1);
            y1 += __shfl_xor_sync(0xffffffffu, y1, 2);

            if (c == 0) {
                int e0 = ebase + g;
                if (e0 < E)     out[e0]     = y0 + b4v;
                if (e0 + 8 < E) out[e0 + 8] = y1 + b4v;
            }
        }
    }
}

// ---------------------------------------------------------------------------
extern "C" void kernel_launch(void* const* d_in, const int* in_sizes, int n_in,
                              void* d_out, int out_size) {
    const float* xd  = (const float*)d_in[0];
    const float* xs  = (const float*)d_in[1];
    const void*  ell = d_in[2];
    const float* W1  = (const float*)d_in[3];
    const float* b1  = (const float*)d_in[4];
    const float* W2  = (const float*)d_in[5];
    const float* b2  = (const float*)d_in[6];
    const float* W3  = (const float*)d_in[7];
    const float* b3  = (const float*)d_in[8];
    const float* W4  = (const float*)d_in[9];
    const float* b4  = (const float*)d_in[10];
    float* out = (float*)d_out;

    int n_drug = in_sizes[0] / 100;
    int n_dis  = in_sizes[1] / 100;
    int E      = in_sizes[2] / 2;
    int nb_drug = (n_drug + NNB - 1) / NNB;
    int nb_dis  = (n_dis  + NNB - 1) / NNB;

    void* sa = nullptr;
    cudaGetSymbolAddress(&sa, g_sync);
    cudaMemsetAsync(sa, 0, 2 * sizeof(unsigned));

    node_precompute<<<14 + nb_drug + nb_dis, 256>>>(
        xd, xs, W1, b1, (const long long*)ell, n_drug, n_dis, nb_drug);

    int n_tiles = (E + EPB - 1) / EPB;
    int grid = 3 * 148;
    if (grid > n_tiles) grid = n_tiles;
    edge_mlp_kernel<<<grid, NTHR>>>(ell, W2, b2, W3, b3, W4, b4,
                                    out, E, n_tiles);
}